// round 2
// baseline (speedup 1.0000x reference)
#include <cuda_runtime.h>
#include <cstdint>

// Problem dims (fixed for this dataset)
#define T_DIM   1000
#define B_DIM   32
#define N_DIM   2048
#define BN      (B_DIM * N_DIM)        // 65536
#define NCHUNK  10
#define CHUNK   (T_DIM / NCHUNK)       // 100
#define THREADS 512
#define NPT     4                       // neurons per thread (float4) -> 512*4 = 2048 = N_DIM

// Output layout (concatenated, tuple order):
// firing_rates[BN] | cv_isi[BN] | synchrony[B] | total_spikes[BN] | active[B]
#define OFF_RATE 0
#define OFF_CV   (BN)
#define OFF_SYNC (2 * BN)
#define OFF_TOT  (2 * BN + B_DIM)
#define OFF_ACT  (3 * BN + B_DIM)

// Scratch (device globals; allocation is forbidden).
// Packed per-(chunk,neuron) segment partial:
//   g_w: tot | first_local<<8 | last_local<<16   (0 if no spikes in chunk)
//   g_s: sum of squared intra-chunk gaps (gaps after the first spike in chunk)
__device__ int g_w  [NCHUNK * BN];
__device__ int g_s  [NCHUNK * BN];
__device__ int g_pop[B_DIM * T_DIM];   // population activity [b][t]; unique writer per (b,t)

// ---------------------------------------------------------------------------
// Kernel 1: streaming pass. Block = one (batch, time-chunk); 512 threads x 4
// neurons covers the full N=2048 row, so the block is the sole writer of its
// g_pop[b][t0..t0+CHUNK) slice (no atomics, no zeroing).
// ISI per neuron in a chunk is an associative segment monoid:
//   (tot, first, last, sum_gap^2); combined later in chunk order.
// ---------------------------------------------------------------------------
__global__ __launch_bounds__(THREADS) void k_main(const float* __restrict__ sp) {
    const int b    = blockIdx.x;
    const int c    = blockIdx.y;
    const int tid  = threadIdx.x;
    const int wid  = tid >> 5;
    const int lane = tid & 31;
    const int n0   = tid * NPT;
    const int t0   = c * CHUNK;

    const float4* __restrict__ p =
        (const float4*)(sp + (size_t)t0 * BN + (size_t)b * N_DIM + n0);
    const size_t stride4 = BN / 4;

    int last0 = -1, last1 = -1, last2 = -1, last3 = -1;
    int fst0 = 127, fst1 = 127, fst2 = 127, fst3 = 127;   // local sentinel > 99
    int tot0 = 0, tot1 = 0, tot2 = 0, tot3 = 0;
    int sg0 = 0, sg1 = 0, sg2 = 0, sg3 = 0;

    __shared__ int s_pop[THREADS / 32][CHUNK];

    #pragma unroll 4
    for (int tl = 0; tl < CHUNK; ++tl) {
        float4 x = p[(size_t)tl * stride4];
        int cc = 0;
        if (x.x != 0.0f) { int g = tl - last0; sg0 += g * g; fst0 = min(fst0, tl); last0 = tl; tot0++; cc++; }
        if (x.y != 0.0f) { int g = tl - last1; sg1 += g * g; fst1 = min(fst1, tl); last1 = tl; tot1++; cc++; }
        if (x.z != 0.0f) { int g = tl - last2; sg2 += g * g; fst2 = min(fst2, tl); last2 = tl; tot2++; cc++; }
        if (x.w != 0.0f) { int g = tl - last3; sg3 += g * g; fst3 = min(fst3, tl); last3 = tl; tot3++; cc++; }
        unsigned wsum = __reduce_add_sync(0xffffffffu, (unsigned)cc);
        if (lane == 0) s_pop[wid][tl] = (int)wsum;
    }

    // remove spurious first-gap (computed against last = -1); pack.
    int w0 = 0, w1 = 0, w2 = 0, w3 = 0;
    if (tot0 > 0) { sg0 -= (fst0 + 1) * (fst0 + 1); w0 = tot0 | (fst0 << 8) | (last0 << 16); }
    if (tot1 > 0) { sg1 -= (fst1 + 1) * (fst1 + 1); w1 = tot1 | (fst1 << 8) | (last1 << 16); }
    if (tot2 > 0) { sg2 -= (fst2 + 1) * (fst2 + 1); w2 = tot2 | (fst2 << 8) | (last2 << 16); }
    if (tot3 > 0) { sg3 -= (fst3 + 1) * (fst3 + 1); w3 = tot3 | (fst3 << 8) | (last3 << 16); }

    const int idx = c * BN + b * N_DIM + n0;     // n0 multiple of 4 -> int4 aligned
    *(int4*)&g_w[idx] = make_int4(w0, w1, w2, w3);
    *(int4*)&g_s[idx] = make_int4(sg0, sg1, sg2, sg3);

    __syncthreads();
    if (tid < CHUNK) {
        int ssum = 0;
        #pragma unroll
        for (int w = 0; w < THREADS / 32; ++w) ssum += s_pop[w][tid];
        g_pop[b * T_DIM + t0 + tid] = ssum;      // unique writer: no atomic
    }
}

// ---------------------------------------------------------------------------
// Kernel 2: fused epilogue. One block per batch.
//  (a) combine the NCHUNK ordered segment partials per neuron -> rate/cv/tot
//  (b) block-reduce active-neuron count (exact integers)
//  (c) lag-1 circular autocorrelation of pop[b][:] from shared memory
// ---------------------------------------------------------------------------
__global__ __launch_bounds__(256) void k_epi(float* __restrict__ out) {
    const int b   = blockIdx.x;
    const int tid = threadIdx.x;
    const int lane = tid & 31;
    const int wid  = tid >> 5;

    __shared__ float  sp[T_DIM];
    __shared__ double redd[2][8];
    __shared__ int    redi[8];

    // prefetch pop into smem early (hides DRAM latency behind the stats work)
    for (int t = tid; t < T_DIM; t += 256)
        sp[t] = (float)g_pop[b * T_DIM + t];

    int actcnt = 0;
    #pragma unroll
    for (int r = 0; r < N_DIM / 256; ++r) {
        const int i = b * N_DIM + r * 256 + tid;     // coalesced across warp

        int tot = 0, fst = 0, lst = 0, sg2 = 0;
        bool any = false;
        #pragma unroll
        for (int c = 0; c < NCHUNK; ++c) {
            int w = g_w[c * BN + i];
            if (w == 0) continue;
            int t  = w & 255;
            int f  = c * CHUNK + ((w >> 8) & 255);
            int l  = c * CHUNK + ((w >> 16) & 255);
            int s2 = g_s[c * BN + i];
            if (!any) { any = true; tot = t; fst = f; lst = l; sg2 = s2; }
            else {
                int g = f - lst;                      // cross-chunk gap
                sg2 += g * g + s2;
                lst = l;
                tot += t;
            }
        }

        float ftot = (float)tot;
        float cv = 0.0f;
        int cnt = tot - 1;
        if (cnt >= 1) {
            float fcnt  = (float)cnt;
            float sum_g = (float)(lst - fst);
            float mean  = sum_g / fcnt;
            float var   = ((float)sg2 - fcnt * mean * mean) / fmaxf(fcnt - 1.0f, 1.0f);
            cv = sqrtf(fmaxf(var, 0.0f)) / fmaxf(mean, 1e-12f);
        }

        out[OFF_RATE + i] = ftot;                    // tot / (1000*0.001) == tot
        out[OFF_CV   + i] = cv;
        out[OFF_TOT  + i] = ftot;
        actcnt += (tot > 0);
    }

    // (b) active-neuron count: warp + block reduce (exact ints)
    actcnt = (int)__reduce_add_sync(0xffffffffu, (unsigned)actcnt);
    if (lane == 0) redi[wid] = actcnt;
    __syncthreads();
    if (tid == 0) {
        int a = 0;
        #pragma unroll
        for (int w = 0; w < 8; ++w) a += redi[w];
        out[OFF_ACT + b] = (float)a;
    }

    // (c) synchrony: mean (exact integer sum), then num / sqrt(Sx*Sy).
    // Sy == Sx exactly (same multiset of values), so den = Sx.
    double s = 0.0;
    for (int t = tid; t < T_DIM; t += 256) s += (double)sp[t];
    for (int o = 16; o > 0; o >>= 1) s += __shfl_down_sync(0xffffffffu, s, o);
    if (lane == 0) redd[0][wid] = s;
    __syncthreads();
    double total = 0.0;
    #pragma unroll
    for (int w = 0; w < 8; ++w) total += redd[0][w];
    const double mean = total / (double)T_DIM;
    __syncthreads();

    double num = 0.0, sx = 0.0;
    for (int t = tid; t < T_DIM; t += 256) {
        double xm = (double)sp[t] - mean;
        double ym = (double)sp[(t == 0) ? (T_DIM - 1) : (t - 1)] - mean;
        num += xm * ym;
        sx  += xm * xm;
    }
    for (int o = 16; o > 0; o >>= 1) {
        num += __shfl_down_sync(0xffffffffu, num, o);
        sx  += __shfl_down_sync(0xffffffffu, sx,  o);
    }
    if (lane == 0) { redd[0][wid] = num; redd[1][wid] = sx; }
    __syncthreads();
    if (tid == 0) {
        double n2 = 0.0, x2 = 0.0;
        #pragma unroll
        for (int w = 0; w < 8; ++w) { n2 += redd[0][w]; x2 += redd[1][w]; }
        float r = 0.0f;
        if (x2 > 0.0) r = (float)(n2 / (x2 > 1e-12 ? x2 : 1e-12));
        out[OFF_SYNC + b] = r;
    }
}

// ---------------------------------------------------------------------------
extern "C" void kernel_launch(void* const* d_in, const int* in_sizes, int n_in,
                              void* d_out, int out_size) {
    const float* sp = (const float*)d_in[0];
    float* out = (float*)d_out;

    dim3 g1(B_DIM, NCHUNK);                    // 32 x 10 blocks, 512 threads
    k_main<<<g1, THREADS>>>(sp);
    k_epi<<<B_DIM, 256>>>(out);
}